// round 11
// baseline (speedup 1.0000x reference)
#include <cuda_runtime.h>
#include <cuda_fp16.h>
#include <math.h>
#include <stdint.h>

#define NT 16384
#define NE 16384
#define BETA 0.25f

#define RH  72                      // halves per padded row (64 data + 8 pad)
#define RBH 144                     // bytes per row (9*16 -> conflict-free ldmatrix)
#define TILEH (128 * RBH)           // 18432
#define CHUNKH (TILEH / 16)         // 1152

#define CAP 128                     // candidate slots per token
#define MK1 4.0e-4f                 // margin slope  (>= 2 * 9.6e-5, 2x pad)
#define MK2 2.0e-4f                 // margin offset (>= 2 * 3e-5, big pad)

// ---------------- static device scratch ----------------
__device__ __half g_zh[16384 * RH];   // zh tiles, padded rows
__device__ __half g_eh[16384 * RH];   // Eh tiles (E = 4096*e), padded rows
__device__ float g_enorm[NE];
__device__ float g_znorm[NT];
__device__ int   g_cand[NT * CAP];
__device__ int   g_ccnt[NT];
__device__ int   g_idx[NT];
__device__ int   g_counts[NE];
__device__ float g_loss;
__device__ float g_ent;
__device__ int   g_cu;
__device__ int   g_tick;

// ---------------- helpers ----------------
__device__ __forceinline__ uint32_t smem_u32(const void* p) {
    uint32_t a;
    asm("{ .reg .u64 t; cvta.to.shared.u64 t, %1; cvt.u32.u64 %0, t; }" : "=r"(a) : "l"(p));
    return a;
}

#define CP_ASYNC16(dst_u32, src_ptr) \
    asm volatile("cp.async.cg.shared.global [%0], [%1], 16;\n" :: "r"(dst_u32), "l"(src_ptr))
#define CP_COMMIT()  asm volatile("cp.async.commit_group;\n" ::: "memory")
#define CP_WAIT0()   asm volatile("cp.async.wait_group 0;\n" ::: "memory")

#define LDSM_X4(r, addr) \
    asm volatile("ldmatrix.sync.aligned.m8n8.x4.shared.b16 {%0,%1,%2,%3}, [%4];" \
        : "=r"((r)[0]), "=r"((r)[1]), "=r"((r)[2]), "=r"((r)[3]) : "r"(addr))
#define LDSM_X2(r, addr) \
    asm volatile("ldmatrix.sync.aligned.m8n8.x2.shared.b16 {%0,%1}, [%2];" \
        : "=r"((r)[0]), "=r"((r)[1]) : "r"(addr))

__device__ __forceinline__ void mma16816(float* c, const uint32_t* a, const uint32_t* b) {
    asm volatile(
        "mma.sync.aligned.m16n8k16.row.col.f32.f16.f16.f32 "
        "{%0,%1,%2,%3}, {%4,%5,%6,%7}, {%8,%9}, {%0,%1,%2,%3};"
        : "+f"(c[0]), "+f"(c[1]), "+f"(c[2]), "+f"(c[3])
        : "r"(a[0]), "r"(a[1]), "r"(a[2]), "r"(a[3]), "r"(b[0]), "r"(b[1]));
}

// ---------------- prep: h-parts only; norms; zero state ----------------
__global__ void k_split(const float* __restrict__ z, const float* __restrict__ emb) {
    extern __shared__ __half st[];          // 128*RH halves = 18432 B
    int blk = blockIdx.x;                   // 0..127 z tiles, 128..255 e subtiles
    int tid = threadIdx.x;                  // 256
    if (blk < 128) {
        int tile = blk;
        int b = tile >> 3, hw0 = (tile & 7) << 7;
        for (int idx = tid; idx < 8192; idx += 256) {
            int k = idx >> 7, tl = idx & 127;
            float v = z[((size_t)(b * 64 + k) << 10) + hw0 + tl];
            st[tl * RH + k] = __float2half_rn(v);
        }
        __syncthreads();
        float4* dst = (float4*)(g_zh + (size_t)tile * 128 * RH);
        const float4* src = (const float4*)st;
        for (int i = tid; i < CHUNKH; i += 256) dst[i] = src[i];
        if (tid < 128) {
            float s = 0.f;
            for (int k = 0; k < 64; k++) {
                float v = z[((size_t)(b * 64 + k) << 10) + hw0 + tid];
                s += v * v;
            }
            g_znorm[(tile << 7) + tid] = s;
        }
        if (tile == 0 && tid == 0) { g_loss = 0.f; g_ent = 0.f; g_cu = 0; g_tick = 0; }
    } else {
        int sub = blk - 128;
        int n0 = sub << 7;
        for (int idx = tid; idx < 8192; idx += 256) {
            int nl = idx >> 6, k = idx & 63;
            float v = emb[(size_t)(n0 + nl) * 64 + k] * 4096.0f;   // exact scale
            st[nl * RH + k] = __float2half_rn(v);
        }
        __syncthreads();
        float4* dst = (float4*)(g_eh + (size_t)sub * 128 * RH);
        const float4* src = (const float4*)st;
        for (int i = tid; i < CHUNKH; i += 256) dst[i] = src[i];
        if (tid < 128) {
            float s = 0.f;
            for (int k = 0; k < 64; k++) {
                float v = emb[(size_t)(n0 + tid) * 64 + k];
                s += v * v;
            }
            g_enorm[n0 + tid] = s;
            g_counts[n0 + tid] = 0;
            g_ccnt[n0 + tid] = 0;
        }
    }
}

// ---------------- building blocks ----------------
__device__ __forceinline__ void load_en(int j, int nbw, int lane, float en[8]) {
#pragma unroll
    for (int ni = 0; ni < 4; ni++) {
        int c0 = nbw + ni * 8 + (lane & 3) * 2;
        en[ni * 2]     = __ldg(&g_enorm[(j << 7) + c0]);
        en[ni * 2 + 1] = __ldg(&g_enorm[(j << 7) + c0 + 1]);
    }
}

// hh-only mma over the K=64 h tiles
__device__ __forceinline__ void mma_phase_h(uint32_t a_base, uint32_t b_base,
                                            float acc[4][4][4]) {
#pragma unroll
    for (int mi = 0; mi < 4; mi++)
#pragma unroll
        for (int ni = 0; ni < 4; ni++)
#pragma unroll
            for (int q = 0; q < 4; q++) acc[mi][ni][q] = 0.f;
#pragma unroll
    for (int ks = 0; ks < 4; ks++) {
        uint32_t ah[4][4], bh[4][2];
#pragma unroll
        for (int mi = 0; mi < 4; mi++)
            LDSM_X4(ah[mi], a_base + mi * 16 * RBH + ks * 32);
#pragma unroll
        for (int ni = 0; ni < 4; ni++)
            LDSM_X2(bh[ni], b_base + ni * 8 * RBH + ks * 32);
#pragma unroll
        for (int mi = 0; mi < 4; mi++)
#pragma unroll
            for (int ni = 0; ni < 4; ni++)
                mma16816(acc[mi][ni], ah[mi], bh[ni]);
    }
}

// ---------------- pass 1: hh filter GEMM + candidate collection -------------------
// smem: A [0,18432) | B0 | B1  (total 55296)
#define SM_F (3 * TILEH)

__global__ void __launch_bounds__(256, 1) k_f() {
    extern __shared__ __align__(16) unsigned char sm[];
    uint32_t sb = smem_u32(sm);
    const uint32_t SA = sb, SB0 = sb + TILEH, SB1 = sb + 2 * TILEH;

    int tid = threadIdx.x, lane = tid & 31, wid = tid >> 5;
    int mw = wid & 1, nw = wid >> 1;        // 2 x 4 warp grid
    int mbase = mw * 64, nbw = nw * 32;     // warp tile 64 x 32

    // prolog: A tile + B subtile 0
    {
        const char* gz = (const char*)(g_zh + (size_t)blockIdx.x * 128 * RH);
        for (int i = tid; i < CHUNKH; i += 256) CP_ASYNC16(SA + i * 16, gz + i * 16);
        const char* ge = (const char*)g_eh;
        for (int i = tid; i < CHUNKH; i += 256) CP_ASYNC16(SB0 + i * 16, ge + i * 16);
        CP_COMMIT(); CP_WAIT0();
    }
    __syncthreads();

    // per-thread rows: r = mbase + mi*16 + rh*8 + (lane>>2); margin per row
    float Mr[8];
#pragma unroll
    for (int mi = 0; mi < 4; mi++)
#pragma unroll
        for (int rh = 0; rh < 2; rh++) {
            float zn = g_znorm[(blockIdx.x << 7) + mbase + mi * 16 + rh * 8 + (lane >> 2)];
            Mr[mi * 2 + rh] = fmaf(sqrtf(zn), MK1, MK2);
        }

    float bv[8];
#pragma unroll
    for (int r = 0; r < 8; r++) bv[r] = 3.0e38f;

    uint32_t a_base = SA + (uint32_t)(mbase + (lane & 15)) * RBH + ((lane >> 4) & 1) * 16;
    uint32_t b_roff = (uint32_t)(nbw + (lane & 7)) * RBH + ((lane >> 3) & 1) * 16;

    int tkbase = (blockIdx.x << 7) + mbase;
    float acc[4][4][4];

    for (int j = 0; j < 128; j++) {
        uint32_t Bcur  = (j & 1) ? SB1 : SB0;
        uint32_t Bnext = (j & 1) ? SB0 : SB1;

        if (j < 127) {
            const char* src = (const char*)(g_eh + (size_t)(j + 1) * 128 * RH);
            for (int i = tid; i < CHUNKH; i += 256) CP_ASYNC16(Bnext + i * 16, src + i * 16);
            CP_COMMIT();
        }

        float en[8];
        load_en(j, nbw, lane, en);

        mma_phase_h(a_base, Bcur + b_roff, acc);

        // filter epilogue: q = en - acc*2^-11 (zn cancels in comparisons).
        // collect n if q <= m_known + M, m_known = quad-shared running min (>= final min).
        int jbase = j << 7;
#pragma unroll
        for (int mi = 0; mi < 4; mi++) {
#pragma unroll
            for (int rh = 0; rh < 2; rh++) {
                int r = mi * 2 + rh;
                float q[4][2];
#pragma unroll
                for (int ni = 0; ni < 4; ni++)
#pragma unroll
                    for (int col = 0; col < 2; col++)
                        q[ni][col] = fmaf(acc[mi][ni][rh * 2 + col], -0x1p-11f,
                                          en[ni * 2 + col]);
                float m8 = fminf(fminf(fminf(q[0][0], q[0][1]), fminf(q[1][0], q[1][1])),
                                 fminf(fminf(q[2][0], q[2][1]), fminf(q[3][0], q[3][1])));
                float m32 = fminf(m8, __shfl_xor_sync(0xffffffffu, m8, 1));
                m32 = fminf(m32, __shfl_xor_sync(0xffffffffu, m32, 2));
                float base = (j == 0) ? m32 : bv[r];
                float thr = base + Mr[r];
                if (m32 <= thr) {
                    int t = tkbase + mi * 16 + rh * 8 + (lane >> 2);
#pragma unroll
                    for (int ni = 0; ni < 4; ni++)
#pragma unroll
                        for (int col = 0; col < 2; col++) {
                            if (q[ni][col] <= thr) {
                                int n = jbase + nbw + ni * 8 + (lane & 3) * 2 + col;
                                int slot = atomicAdd(&g_ccnt[t], 1);
                                if (slot < CAP) g_cand[t * CAP + slot] = n;
                            }
                        }
                }
                bv[r] = (j == 0) ? m32 : fminf(bv[r], m32);
            }
        }

        CP_WAIT0();
        __syncthreads();
    }
}

// ---------------- pass 2: exact fp32 refine over candidates (R1 formula) -----------
__global__ void k_refine(const float* __restrict__ z, const float* __restrict__ emb,
                         float* __restrict__ out) {
    __shared__ float zs[8][64];
    int w = threadIdx.x >> 5, lane = threadIdx.x & 31;
    int t = blockIdx.x * 8 + w;
    int b = t >> 10, hw = t & 1023;
    zs[w][lane]      = z[((size_t)(b * 64 + lane) << 10) + hw];
    zs[w][lane + 32] = z[((size_t)(b * 64 + lane + 32) << 10) + hw];
    __syncwarp();
    float zn = g_znorm[t];
    int c = g_ccnt[t];
    float bd = 3.0e38f; int bn = 0x7fffffff;
    if (c <= CAP) {
        for (int i = lane; i < c; i += 32) {
            int n = g_cand[t * CAP + i];
            const float* er = emb + (size_t)n * 64;
            float acc = 0.f;
#pragma unroll
            for (int k = 0; k < 64; k++) acc = fmaf(zs[w][k], er[k], acc);
            float d = __fsub_rn(__fadd_rn(zn, g_enorm[n]), __fmul_rn(2.0f, acc));
            if (d < bd || (d == bd && n < bn)) { bd = d; bn = n; }
        }
    } else {
        // overflow fallback: exact scan of all codes (never expected; correctness net)
        for (int n = lane; n < NE; n += 32) {
            const float* er = emb + (size_t)n * 64;
            float acc = 0.f;
#pragma unroll
            for (int k = 0; k < 64; k++) acc = fmaf(zs[w][k], er[k], acc);
            float d = __fsub_rn(__fadd_rn(zn, g_enorm[n]), __fmul_rn(2.0f, acc));
            if (d < bd || (d == bd && n < bn)) { bd = d; bn = n; }
        }
    }
#pragma unroll
    for (int off = 16; off > 0; off >>= 1) {
        float od = __shfl_xor_sync(0xffffffffu, bd, off);
        int   on = __shfl_xor_sync(0xffffffffu, bn, off);
        if (od < bd || (od == bd && on < bn)) { bd = od; bn = on; }
    }
    if (lane == 0) {
        g_idx[t] = bn;
        out[1048579 + t] = (float)bn;
        atomicAdd(&g_counts[bn], 1);
    }
}

// ---------------- z_q gather + loss accumulation ----------------
__global__ void k_zq(const float* __restrict__ z, const float* __restrict__ emb,
                     float* __restrict__ out) {
    int p = blockIdx.x;            // 1024 planes = (b,c)
    int b = p >> 6, c = p & 63;
    int tid = threadIdx.x;         // 256
    float ls = 0.f;
    for (int hw = tid; hw < 1024; hw += 256) {
        int t = (b << 10) + hw;
        int id = g_idx[t];
        float v  = emb[(size_t)id * 64 + c];
        float zv = z[(size_t)p * 1024 + hw];
        out[(size_t)p * 1024 + hw] = v;
        float df = v - zv;
        ls += df * df;
    }
    __shared__ float red[8];
    for (int o = 16; o > 0; o >>= 1) ls += __shfl_down_sync(0xffffffff, ls, o);
    if ((tid & 31) == 0) red[tid >> 5] = ls;
    __syncthreads();
    if (tid == 0) {
        float s = 0.f;
        for (int w = 0; w < 8; w++) s += red[w];
        atomicAdd(&g_loss, s);
    }
}

// ---------------- entropy (parallel) + final scalar writes (ticket) ----------------
__global__ void k_ent(float* __restrict__ out) {
    int tid = threadIdx.x;                      // 1024, grid 16
    int n = blockIdx.x * 1024 + tid;
    int c = g_counts[n];
    float avg = (float)c * (1.0f / 16384.0f);
    float term = avg * logf(avg + 1e-10f);
    int cu = (c > 0) ? 1 : 0;
    for (int o = 16; o > 0; o >>= 1) {
        term += __shfl_down_sync(0xffffffffu, term, o);
        cu   += __shfl_down_sync(0xffffffffu, cu, o);
    }
    __shared__ float se[32]; __shared__ int sc[32];
    if ((tid & 31) == 0) { se[tid >> 5] = term; sc[tid >> 5] = cu; }
    __syncthreads();
    if (tid == 0) {
        float s = 0.f; int k = 0;
        for (int w = 0; w < 32; w++) { s += se[w]; k += sc[w]; }
        atomicAdd(&g_ent, s);
        atomicAdd(&g_cu, k);
        __threadfence();
        int tk = atomicAdd(&g_tick, 1);
        if (tk == 15) {
            out[1048576] = g_loss * (1.0f + BETA) / 1048576.0f;
            out[1048577] = expf(-g_ent);
            out[1048578] = (float)g_cu;
        }
    }
}

// ---------------- launch ----------------
extern "C" void kernel_launch(void* const* d_in, const int* in_sizes, int n_in,
                              void* d_out, int out_size) {
    const float* z   = (const float*)d_in[0];   // (16,64,32,32)
    const float* emb = (const float*)d_in[1];   // (16384,64)
    float* out = (float*)d_out;

    cudaFuncSetAttribute(k_split, cudaFuncAttributeMaxDynamicSharedMemorySize, TILEH);
    cudaFuncSetAttribute(k_f,     cudaFuncAttributeMaxDynamicSharedMemorySize, SM_F);

    k_split<<<256, 256, TILEH>>>(z, emb);
    k_f<<<128, 256, SM_F>>>();
    k_refine<<<2048, 256>>>(z, emb, out);
    k_zq<<<1024, 256>>>(z, emb, out);
    k_ent<<<16, 1024>>>(out);
}

// round 12
// speedup vs baseline: 1.6905x; 1.6905x over previous
#include <cuda_runtime.h>
#include <cuda_fp16.h>
#include <math.h>
#include <stdint.h>

#define NT 16384
#define NE 16384
#define BETA 0.25f

#define RH  72                      // halves per padded row (64 data + 8 pad)
#define RBH 144                     // bytes per row (9*16 -> conflict-free ldmatrix)
#define TILEH (128 * RBH)           // 18432
#define CHUNKH (TILEH / 16)         // 1152

#define CAP 128                     // candidate slots per token
#define MK1 4.0e-4f                 // margin slope  (>= 2 * 9.5e-5)
#define MK2 2.0e-4f                 // margin offset (>> accumulation rounding)

// ---------------- static device scratch ----------------
__device__ __half g_zh[16384 * RH];   // zh tiles, padded rows
__device__ __half g_eh[16384 * RH];   // Eh tiles (E = 4096*e), padded rows
__device__ float g_enorm[NE];
__device__ float g_znorm[NT];
__device__ float g_thr[NT];           // final hh-min + margin
__device__ int   g_cand[NT * CAP];
__device__ int   g_ccnt[NT];
__device__ int   g_idx[NT];
__device__ int   g_counts[NE];
__device__ float g_loss;
__device__ float g_ent;
__device__ int   g_cu;
__device__ int   g_tick;

// ---------------- helpers ----------------
__device__ __forceinline__ uint32_t smem_u32(const void* p) {
    uint32_t a;
    asm("{ .reg .u64 t; cvta.to.shared.u64 t, %1; cvt.u32.u64 %0, t; }" : "=r"(a) : "l"(p));
    return a;
}

#define CP_ASYNC16(dst_u32, src_ptr) \
    asm volatile("cp.async.cg.shared.global [%0], [%1], 16;\n" :: "r"(dst_u32), "l"(src_ptr))
#define CP_COMMIT()  asm volatile("cp.async.commit_group;\n" ::: "memory")
#define CP_WAIT0()   asm volatile("cp.async.wait_group 0;\n" ::: "memory")

#define LDSM_X4(r, addr) \
    asm volatile("ldmatrix.sync.aligned.m8n8.x4.shared.b16 {%0,%1,%2,%3}, [%4];" \
        : "=r"((r)[0]), "=r"((r)[1]), "=r"((r)[2]), "=r"((r)[3]) : "r"(addr))
#define LDSM_X2(r, addr) \
    asm volatile("ldmatrix.sync.aligned.m8n8.x2.shared.b16 {%0,%1}, [%2];" \
        : "=r"((r)[0]), "=r"((r)[1]) : "r"(addr))

__device__ __forceinline__ void mma16816(float* c, const uint32_t* a, const uint32_t* b) {
    asm volatile(
        "mma.sync.aligned.m16n8k16.row.col.f32.f16.f16.f32 "
        "{%0,%1,%2,%3}, {%4,%5,%6,%7}, {%8,%9}, {%0,%1,%2,%3};"
        : "+f"(c[0]), "+f"(c[1]), "+f"(c[2]), "+f"(c[3])
        : "r"(a[0]), "r"(a[1]), "r"(a[2]), "r"(a[3]), "r"(b[0]), "r"(b[1]));
}

// ---------------- prep: h-parts only; norms; zero state ----------------
__global__ void k_split(const float* __restrict__ z, const float* __restrict__ emb) {
    extern __shared__ __half st[];          // 128*RH halves = 18432 B
    int blk = blockIdx.x;                   // 0..127 z tiles, 128..255 e subtiles
    int tid = threadIdx.x;                  // 256
    if (blk < 128) {
        int tile = blk;
        int b = tile >> 3, hw0 = (tile & 7) << 7;
        for (int idx = tid; idx < 8192; idx += 256) {
            int k = idx >> 7, tl = idx & 127;
            float v = z[((size_t)(b * 64 + k) << 10) + hw0 + tl];
            st[tl * RH + k] = __float2half_rn(v);
        }
        __syncthreads();
        float4* dst = (float4*)(g_zh + (size_t)tile * 128 * RH);
        const float4* src = (const float4*)st;
        for (int i = tid; i < CHUNKH; i += 256) dst[i] = src[i];
        if (tid < 128) {
            float s = 0.f;
            for (int k = 0; k < 64; k++) {
                float v = z[((size_t)(b * 64 + k) << 10) + hw0 + tid];
                s += v * v;
            }
            g_znorm[(tile << 7) + tid] = s;
        }
        if (tile == 0 && tid == 0) { g_loss = 0.f; g_ent = 0.f; g_cu = 0; g_tick = 0; }
    } else {
        int sub = blk - 128;
        int n0 = sub << 7;
        for (int idx = tid; idx < 8192; idx += 256) {
            int nl = idx >> 6, k = idx & 63;
            float v = emb[(size_t)(n0 + nl) * 64 + k] * 4096.0f;   // exact scale
            st[nl * RH + k] = __float2half_rn(v);
        }
        __syncthreads();
        float4* dst = (float4*)(g_eh + (size_t)sub * 128 * RH);
        const float4* src = (const float4*)st;
        for (int i = tid; i < CHUNKH; i += 256) dst[i] = src[i];
        if (tid < 128) {
            float s = 0.f;
            for (int k = 0; k < 64; k++) {
                float v = emb[(size_t)(n0 + tid) * 64 + k];
                s += v * v;
            }
            g_enorm[n0 + tid] = s;
            g_counts[n0 + tid] = 0;
            g_ccnt[n0 + tid] = 0;
        }
    }
}

// ---------------- building blocks ----------------
__device__ __forceinline__ void load_en(int j, int nbw, int lane, float en[8]) {
#pragma unroll
    for (int ni = 0; ni < 4; ni++) {
        int c0 = nbw + ni * 8 + (lane & 3) * 2;
        en[ni * 2]     = __ldg(&g_enorm[(j << 7) + c0]);
        en[ni * 2 + 1] = __ldg(&g_enorm[(j << 7) + c0 + 1]);
    }
}

// hh-only mma over the K=64 h tiles
__device__ __forceinline__ void mma_phase_h(uint32_t a_base, uint32_t b_base,
                                            float acc[4][4][4]) {
#pragma unroll
    for (int mi = 0; mi < 4; mi++)
#pragma unroll
        for (int ni = 0; ni < 4; ni++)
#pragma unroll
            for (int q = 0; q < 4; q++) acc[mi][ni][q] = 0.f;
#pragma unroll
    for (int ks = 0; ks < 4; ks++) {
        uint32_t ah[4][4], bh[4][2];
#pragma unroll
        for (int mi = 0; mi < 4; mi++)
            LDSM_X4(ah[mi], a_base + mi * 16 * RBH + ks * 32);
#pragma unroll
        for (int ni = 0; ni < 4; ni++)
            LDSM_X2(bh[ni], b_base + ni * 8 * RBH + ks * 32);
#pragma unroll
        for (int mi = 0; mi < 4; mi++)
#pragma unroll
            for (int ni = 0; ni < 4; ni++)
                mma16816(acc[mi][ni], ah[mi], bh[ni]);
    }
}

// ---------------- pass A: hh GEMM, value-only min -> g_thr ------------------------
// smem: A [0,18432) | B0 | B1  (total 55296)
#define SM_F (3 * TILEH)

__global__ void __launch_bounds__(256, 1) k_min() {
    extern __shared__ __align__(16) unsigned char sm[];
    uint32_t sb = smem_u32(sm);
    const uint32_t SA = sb, SB0 = sb + TILEH, SB1 = sb + 2 * TILEH;

    int tid = threadIdx.x, lane = tid & 31, wid = tid >> 5;
    int mw = wid & 1, nw = wid >> 1;        // 2 x 4 warp grid
    int mbase = mw * 64, nbw = nw * 32;     // warp tile 64 x 32

    {
        const char* gz = (const char*)(g_zh + (size_t)blockIdx.x * 128 * RH);
        for (int i = tid; i < CHUNKH; i += 256) CP_ASYNC16(SA + i * 16, gz + i * 16);
        const char* ge = (const char*)g_eh;
        for (int i = tid; i < CHUNKH; i += 256) CP_ASYNC16(SB0 + i * 16, ge + i * 16);
        CP_COMMIT(); CP_WAIT0();
    }
    __syncthreads();

    float bv[8];
#pragma unroll
    for (int r = 0; r < 8; r++) bv[r] = 3.0e38f;

    uint32_t a_base = SA + (uint32_t)(mbase + (lane & 15)) * RBH + ((lane >> 4) & 1) * 16;
    uint32_t b_roff = (uint32_t)(nbw + (lane & 7)) * RBH + ((lane >> 3) & 1) * 16;

    float acc[4][4][4];

    for (int j = 0; j < 128; j++) {
        uint32_t Bcur  = (j & 1) ? SB1 : SB0;
        uint32_t Bnext = (j & 1) ? SB0 : SB1;

        if (j < 127) {
            const char* src = (const char*)(g_eh + (size_t)(j + 1) * 128 * RH);
            for (int i = tid; i < CHUNKH; i += 256) CP_ASYNC16(Bnext + i * 16, src + i * 16);
            CP_COMMIT();
        }

        float en[8];
        load_en(j, nbw, lane, en);

        mma_phase_h(a_base, Bcur + b_roff, acc);

        // min epilogue: q = en - acc*2^-11 (zn cancels); value-only
#pragma unroll
        for (int mi = 0; mi < 4; mi++) {
#pragma unroll
            for (int rh = 0; rh < 2; rh++) {
                float q0 = fmaf(acc[mi][0][rh * 2 + 0], -0x1p-11f, en[0]);
                float q1 = fmaf(acc[mi][0][rh * 2 + 1], -0x1p-11f, en[1]);
                float q2 = fmaf(acc[mi][1][rh * 2 + 0], -0x1p-11f, en[2]);
                float q3 = fmaf(acc[mi][1][rh * 2 + 1], -0x1p-11f, en[3]);
                float q4 = fmaf(acc[mi][2][rh * 2 + 0], -0x1p-11f, en[4]);
                float q5 = fmaf(acc[mi][2][rh * 2 + 1], -0x1p-11f, en[5]);
                float q6 = fmaf(acc[mi][3][rh * 2 + 0], -0x1p-11f, en[6]);
                float q7 = fmaf(acc[mi][3][rh * 2 + 1], -0x1p-11f, en[7]);
                float m8 = fminf(fminf(fminf(q0, q1), fminf(q2, q3)),
                                 fminf(fminf(q4, q5), fminf(q6, q7)));
                bv[mi * 2 + rh] = fminf(bv[mi * 2 + rh], m8);
            }
        }

        CP_WAIT0();
        __syncthreads();
    }

    // quad reduce then cross-warp reduce -> per-token threshold
#pragma unroll
    for (int r = 0; r < 8; r++) {
        bv[r] = fminf(bv[r], __shfl_xor_sync(0xffffffffu, bv[r], 1));
        bv[r] = fminf(bv[r], __shfl_xor_sync(0xffffffffu, bv[r], 2));
    }
    __syncthreads();
    float* rv = (float*)sm;                          // 128 rows x 4 nwarps
    if ((lane & 3) == 0) {
#pragma unroll
        for (int r = 0; r < 8; r++) {
            int row = mbase + (r >> 1) * 16 + (r & 1) * 8 + (lane >> 2);
            rv[row * 4 + nw] = bv[r];
        }
    }
    __syncthreads();
    if (tid < 128) {
        float v = fminf(fminf(rv[tid * 4], rv[tid * 4 + 1]),
                        fminf(rv[tid * 4 + 2], rv[tid * 4 + 3]));
        int t = (blockIdx.x << 7) + tid;
        float zn = g_znorm[t];
        g_thr[t] = v + fmaf(sqrtf(zn), MK1, MK2);
    }
}

// ---------------- pass B: hh GEMM, collect candidates vs final threshold ----------
__global__ void __launch_bounds__(256, 1) k_coll() {
    extern __shared__ __align__(16) unsigned char sm[];
    uint32_t sb = smem_u32(sm);
    const uint32_t SA = sb, SB0 = sb + TILEH, SB1 = sb + 2 * TILEH;

    int tid = threadIdx.x, lane = tid & 31, wid = tid >> 5;
    int mw = wid & 1, nw = wid >> 1;
    int mbase = mw * 64, nbw = nw * 32;

    {
        const char* gz = (const char*)(g_zh + (size_t)blockIdx.x * 128 * RH);
        for (int i = tid; i < CHUNKH; i += 256) CP_ASYNC16(SA + i * 16, gz + i * 16);
        const char* ge = (const char*)g_eh;
        for (int i = tid; i < CHUNKH; i += 256) CP_ASYNC16(SB0 + i * 16, ge + i * 16);
        CP_COMMIT(); CP_WAIT0();
    }
    __syncthreads();

    // per-row final thresholds (tight: min + margin)
    float thr[8]; int tok[8];
#pragma unroll
    for (int mi = 0; mi < 4; mi++)
#pragma unroll
        for (int rh = 0; rh < 2; rh++) {
            int t = (blockIdx.x << 7) + mbase + mi * 16 + rh * 8 + (lane >> 2);
            tok[mi * 2 + rh] = t;
            thr[mi * 2 + rh] = g_thr[t];
        }

    uint32_t a_base = SA + (uint32_t)(mbase + (lane & 15)) * RBH + ((lane >> 4) & 1) * 16;
    uint32_t b_roff = (uint32_t)(nbw + (lane & 7)) * RBH + ((lane >> 3) & 1) * 16;

    float acc[4][4][4];

    for (int j = 0; j < 128; j++) {
        uint32_t Bcur  = (j & 1) ? SB1 : SB0;
        uint32_t Bnext = (j & 1) ? SB0 : SB1;

        if (j < 127) {
            const char* src = (const char*)(g_eh + (size_t)(j + 1) * 128 * RH);
            for (int i = tid; i < CHUNKH; i += 256) CP_ASYNC16(Bnext + i * 16, src + i * 16);
            CP_COMMIT();
        }

        float en[8];
        load_en(j, nbw, lane, en);

        mma_phase_h(a_base, Bcur + b_roff, acc);

        int jbase = j << 7;
#pragma unroll
        for (int mi = 0; mi < 4; mi++) {
#pragma unroll
            for (int rh = 0; rh < 2; rh++) {
                int r = mi * 2 + rh;
                float q[4][2];
#pragma unroll
                for (int ni = 0; ni < 4; ni++)
#pragma unroll
                    for (int col = 0; col < 2; col++)
                        q[ni][col] = fmaf(acc[mi][ni][rh * 2 + col], -0x1p-11f,
                                          en[ni * 2 + col]);
                float m8 = fminf(fminf(fminf(q[0][0], q[0][1]), fminf(q[1][0], q[1][1])),
                                 fminf(fminf(q[2][0], q[2][1]), fminf(q[3][0], q[3][1])));
                if (m8 <= thr[r]) {     // rare: threshold is final min + small margin
                    int t = tok[r];
#pragma unroll
                    for (int ni = 0; ni < 4; ni++)
#pragma unroll
                        for (int col = 0; col < 2; col++) {
                            if (q[ni][col] <= thr[r]) {
                                int n = jbase + nbw + ni * 8 + (lane & 3) * 2 + col;
                                int slot = atomicAdd(&g_ccnt[t], 1);
                                if (slot < CAP) g_cand[t * CAP + slot] = n;
                            }
                        }
                }
            }
        }

        CP_WAIT0();
        __syncthreads();
    }
}

// ---------------- pass C: exact fp32 refine over candidates (R1 formula) -----------
__global__ void k_refine(const float* __restrict__ z, const float* __restrict__ emb,
                         float* __restrict__ out) {
    __shared__ float zs[8][64];
    int w = threadIdx.x >> 5, lane = threadIdx.x & 31;
    int t = blockIdx.x * 8 + w;
    int b = t >> 10, hw = t & 1023;
    zs[w][lane]      = z[((size_t)(b * 64 + lane) << 10) + hw];
    zs[w][lane + 32] = z[((size_t)(b * 64 + lane + 32) << 10) + hw];
    __syncwarp();
    float zn = g_znorm[t];
    int c = g_ccnt[t];
    float bd = 3.0e38f; int bn = 0x7fffffff;
    if (c <= CAP) {
        for (int i = lane; i < c; i += 32) {
            int n = g_cand[t * CAP + i];
            const float* er = emb + (size_t)n * 64;
            float acc = 0.f;
#pragma unroll
            for (int k = 0; k < 64; k++) acc = fmaf(zs[w][k], er[k], acc);
            float d = __fsub_rn(__fadd_rn(zn, g_enorm[n]), __fmul_rn(2.0f, acc));
            if (d < bd || (d == bd && n < bn)) { bd = d; bn = n; }
        }
    } else {
        // overflow fallback: exact scan of all codes (correctness net)
        for (int n = lane; n < NE; n += 32) {
            const float* er = emb + (size_t)n * 64;
            float acc = 0.f;
#pragma unroll
            for (int k = 0; k < 64; k++) acc = fmaf(zs[w][k], er[k], acc);
            float d = __fsub_rn(__fadd_rn(zn, g_enorm[n]), __fmul_rn(2.0f, acc));
            if (d < bd || (d == bd && n < bn)) { bd = d; bn = n; }
        }
    }
#pragma unroll
    for (int off = 16; off > 0; off >>= 1) {
        float od = __shfl_xor_sync(0xffffffffu, bd, off);
        int   on = __shfl_xor_sync(0xffffffffu, bn, off);
        if (od < bd || (od == bd && on < bn)) { bd = od; bn = on; }
    }
    if (lane == 0) {
        g_idx[t] = bn;
        out[1048579 + t] = (float)bn;
        atomicAdd(&g_counts[bn], 1);
    }
}

// ---------------- z_q gather + loss accumulation ----------------
__global__ void k_zq(const float* __restrict__ z, const float* __restrict__ emb,
                     float* __restrict__ out) {
    int p = blockIdx.x;            // 1024 planes = (b,c)
    int b = p >> 6, c = p & 63;
    int tid = threadIdx.x;         // 256
    float ls = 0.f;
    for (int hw = tid; hw < 1024; hw += 256) {
        int t = (b << 10) + hw;
        int id = g_idx[t];
        float v  = emb[(size_t)id * 64 + c];
        float zv = z[(size_t)p * 1024 + hw];
        out[(size_t)p * 1024 + hw] = v;
        float df = v - zv;
        ls += df * df;
    }
    __shared__ float red[8];
    for (int o = 16; o > 0; o >>= 1) ls += __shfl_down_sync(0xffffffff, ls, o);
    if ((tid & 31) == 0) red[tid >> 5] = ls;
    __syncthreads();
    if (tid == 0) {
        float s = 0.f;
        for (int w = 0; w < 8; w++) s += red[w];
        atomicAdd(&g_loss, s);
    }
}

// ---------------- entropy (parallel) + final scalar writes (ticket) ----------------
__global__ void k_ent(float* __restrict__ out) {
    int tid = threadIdx.x;                      // 1024, grid 16
    int n = blockIdx.x * 1024 + tid;
    int c = g_counts[n];
    float avg = (float)c * (1.0f / 16384.0f);
    float term = avg * logf(avg + 1e-10f);
    int cu = (c > 0) ? 1 : 0;
    for (int o = 16; o > 0; o >>= 1) {
        term += __shfl_down_sync(0xffffffffu, term, o);
        cu   += __shfl_down_sync(0xffffffffu, cu, o);
    }
    __shared__ float se[32]; __shared__ int sc[32];
    if ((tid & 31) == 0) { se[tid >> 5] = term; sc[tid >> 5] = cu; }
    __syncthreads();
    if (tid == 0) {
        float s = 0.f; int k = 0;
        for (int w = 0; w < 32; w++) { s += se[w]; k += sc[w]; }
        atomicAdd(&g_ent, s);
        atomicAdd(&g_cu, k);
        __threadfence();
        int tk = atomicAdd(&g_tick, 1);
        if (tk == 15) {
            out[1048576] = g_loss * (1.0f + BETA) / 1048576.0f;
            out[1048577] = expf(-g_ent);
            out[1048578] = (float)g_cu;
        }
    }
}

// ---------------- launch ----------------
extern "C" void kernel_launch(void* const* d_in, const int* in_sizes, int n_in,
                              void* d_out, int out_size) {
    const float* z   = (const float*)d_in[0];   // (16,64,32,32)
    const float* emb = (const float*)d_in[1];   // (16384,64)
    float* out = (float*)d_out;

    cudaFuncSetAttribute(k_split, cudaFuncAttributeMaxDynamicSharedMemorySize, TILEH);
    cudaFuncSetAttribute(k_min,   cudaFuncAttributeMaxDynamicSharedMemorySize, SM_F);
    cudaFuncSetAttribute(k_coll,  cudaFuncAttributeMaxDynamicSharedMemorySize, SM_F);

    k_split<<<256, 256, TILEH>>>(z, emb);
    k_min<<<128, 256, SM_F>>>();
    k_coll<<<128, 256, SM_F>>>();
    k_refine<<<2048, 256>>>(z, emb, out);
    k_zq<<<1024, 256>>>(z, emb, out);
    k_ent<<<16, 1024>>>(out);
}

// round 13
// speedup vs baseline: 1.7870x; 1.0571x over previous
#include <cuda_runtime.h>
#include <cuda_fp16.h>
#include <math.h>
#include <stdint.h>

#define NT 16384
#define NE 16384
#define BETA 0.25f

#define RH  72                      // halves per padded row (64 data + 8 pad)
#define RBH 144                     // bytes per row (9*16 -> conflict-free ldmatrix)
#define TILEH (128 * RBH)           // 18432
#define CHUNKH (TILEH / 16)         // 1152

#define CAP 128                     // candidate slots per token
#define MK1 4.0e-4f                 // margin slope * sqrt(zn)  (hh truncation)
#define MK2 7.0e-3f                 // margin offset (fp16-acc error + slack)

// ---------------- static device scratch ----------------
__device__ __half g_zh[16384 * RH];   // zh tiles, padded rows
__device__ __half g_eh[16384 * RH];   // Eh tiles (E = 4096*e), padded rows
__device__ float g_enorm[NE];
__device__ float g_znorm[NT];
__device__ float g_thr[NT];           // final hh-min + margin
__device__ int   g_cand[NT * CAP];
__device__ int   g_ccnt[NT];
__device__ int   g_idx[NT];
__device__ int   g_counts[NE];
__device__ float g_loss;
__device__ float g_ent;
__device__ int   g_cu;
__device__ int   g_tick;

// ---------------- helpers ----------------
__device__ __forceinline__ uint32_t smem_u32(const void* p) {
    uint32_t a;
    asm("{ .reg .u64 t; cvta.to.shared.u64 t, %1; cvt.u32.u64 %0, t; }" : "=r"(a) : "l"(p));
    return a;
}
__device__ __forceinline__ float2 h2f(uint32_t u) {
    __half2 h = *reinterpret_cast<__half2*>(&u);
    return __half22float2(h);
}

#define CP_ASYNC16(dst_u32, src_ptr) \
    asm volatile("cp.async.cg.shared.global [%0], [%1], 16;\n" :: "r"(dst_u32), "l"(src_ptr))
#define CP_COMMIT()  asm volatile("cp.async.commit_group;\n" ::: "memory")
#define CP_WAIT0()   asm volatile("cp.async.wait_group 0;\n" ::: "memory")

#define LDSM_X4(r, addr) \
    asm volatile("ldmatrix.sync.aligned.m8n8.x4.shared.b16 {%0,%1,%2,%3}, [%4];" \
        : "=r"((r)[0]), "=r"((r)[1]), "=r"((r)[2]), "=r"((r)[3]) : "r"(addr))
#define LDSM_X2(r, addr) \
    asm volatile("ldmatrix.sync.aligned.m8n8.x2.shared.b16 {%0,%1}, [%2];" \
        : "=r"((r)[0]), "=r"((r)[1]) : "r"(addr))

// fp16-accumulate mma (double-rate vs f32-acc)
__device__ __forceinline__ void mma16816h(uint32_t* c, const uint32_t* a, const uint32_t* b) {
    asm volatile(
        "mma.sync.aligned.m16n8k16.row.col.f16.f16.f16.f16 "
        "{%0,%1}, {%2,%3,%4,%5}, {%6,%7}, {%0,%1};"
        : "+r"(c[0]), "+r"(c[1])
        : "r"(a[0]), "r"(a[1]), "r"(a[2]), "r"(a[3]), "r"(b[0]), "r"(b[1]));
}

// ---------------- prep: h-parts only; norms; zero state ----------------
__global__ void k_split(const float* __restrict__ z, const float* __restrict__ emb) {
    extern __shared__ __half st[];          // 128*RH halves = 18432 B
    int blk = blockIdx.x;                   // 0..127 z tiles, 128..255 e subtiles
    int tid = threadIdx.x;                  // 256
    if (blk < 128) {
        int tile = blk;
        int b = tile >> 3, hw0 = (tile & 7) << 7;
        for (int idx = tid; idx < 8192; idx += 256) {
            int k = idx >> 7, tl = idx & 127;
            float v = z[((size_t)(b * 64 + k) << 10) + hw0 + tl];
            st[tl * RH + k] = __float2half_rn(v);
        }
        __syncthreads();
        float4* dst = (float4*)(g_zh + (size_t)tile * 128 * RH);
        const float4* src = (const float4*)st;
        for (int i = tid; i < CHUNKH; i += 256) dst[i] = src[i];
        if (tid < 128) {
            float s = 0.f;
            for (int k = 0; k < 64; k++) {
                float v = z[((size_t)(b * 64 + k) << 10) + hw0 + tid];
                s += v * v;
            }
            g_znorm[(tile << 7) + tid] = s;
        }
        if (tile == 0 && tid == 0) { g_loss = 0.f; g_ent = 0.f; g_cu = 0; g_tick = 0; }
    } else {
        int sub = blk - 128;
        int n0 = sub << 7;
        for (int idx = tid; idx < 8192; idx += 256) {
            int nl = idx >> 6, k = idx & 63;
            float v = emb[(size_t)(n0 + nl) * 64 + k] * 4096.0f;   // exact scale
            st[nl * RH + k] = __float2half_rn(v);
        }
        __syncthreads();
        float4* dst = (float4*)(g_eh + (size_t)sub * 128 * RH);
        const float4* src = (const float4*)st;
        for (int i = tid; i < CHUNKH; i += 256) dst[i] = src[i];
        if (tid < 128) {
            float s = 0.f;
            for (int k = 0; k < 64; k++) {
                float v = emb[(size_t)(n0 + tid) * 64 + k];
                s += v * v;
            }
            g_enorm[n0 + tid] = s;
            g_counts[n0 + tid] = 0;
            g_ccnt[n0 + tid] = 0;
        }
    }
}

// ---------------- building blocks ----------------
__device__ __forceinline__ void load_en(int j, int nbw, int lane, float en[8]) {
#pragma unroll
    for (int ni = 0; ni < 4; ni++) {
        int c0 = nbw + ni * 8 + (lane & 3) * 2;
        en[ni * 2]     = __ldg(&g_enorm[(j << 7) + c0]);
        en[ni * 2 + 1] = __ldg(&g_enorm[(j << 7) + c0 + 1]);
    }
}

// hh-only fp16-acc mma over the K=64 h tiles; acc[mi][ni][rh] = half2 (2 cols)
__device__ __forceinline__ void mma_phase_h16(uint32_t a_base, uint32_t b_base,
                                              uint32_t acc[4][4][2]) {
#pragma unroll
    for (int mi = 0; mi < 4; mi++)
#pragma unroll
        for (int ni = 0; ni < 4; ni++) { acc[mi][ni][0] = 0u; acc[mi][ni][1] = 0u; }
#pragma unroll
    for (int ks = 0; ks < 4; ks++) {
        uint32_t ah[4][4], bh[4][2];
#pragma unroll
        for (int mi = 0; mi < 4; mi++)
            LDSM_X4(ah[mi], a_base + mi * 16 * RBH + ks * 32);
#pragma unroll
        for (int ni = 0; ni < 4; ni++)
            LDSM_X2(bh[ni], b_base + ni * 8 * RBH + ks * 32);
#pragma unroll
        for (int mi = 0; mi < 4; mi++)
#pragma unroll
            for (int ni = 0; ni < 4; ni++)
                mma16816h(acc[mi][ni], ah[mi], bh[ni]);
    }
}

// ---------------- pass A: hh GEMM (f16 acc), value-only min -> g_thr ---------------
// smem: A [0,18432) | B ring x4  (total 92160)
#define SM_F (5 * TILEH)

__global__ void __launch_bounds__(256, 1) k_min() {
    extern __shared__ __align__(16) unsigned char sm[];
    uint32_t sb = smem_u32(sm);
    const uint32_t SA = sb, SBB = sb + TILEH;

    int tid = threadIdx.x, lane = tid & 31, wid = tid >> 5;
    int mw = wid & 1, nw = wid >> 1;        // 2 x 4 warp grid
    int mbase = mw * 64, nbw = nw * 32;     // warp tile 64 x 32

    {
        const char* gz = (const char*)(g_zh + (size_t)blockIdx.x * 128 * RH);
        for (int i = tid; i < CHUNKH; i += 256) CP_ASYNC16(SA + i * 16, gz + i * 16);
        const char* ge0 = (const char*)g_eh;
        for (int i = tid; i < CHUNKH; i += 256) CP_ASYNC16(SBB + i * 16, ge0 + i * 16);
        const char* ge1 = (const char*)(g_eh + (size_t)128 * RH);
        for (int i = tid; i < CHUNKH; i += 256) CP_ASYNC16(SBB + TILEH + i * 16, ge1 + i * 16);
        CP_COMMIT(); CP_WAIT0();
    }
    __syncthreads();

    float bv[8];
#pragma unroll
    for (int r = 0; r < 8; r++) bv[r] = 3.0e38f;

    uint32_t a_base = SA + (uint32_t)(mbase + (lane & 15)) * RBH + ((lane >> 4) & 1) * 16;
    uint32_t b_roff = (uint32_t)(nbw + (lane & 7)) * RBH + ((lane >> 3) & 1) * 16;

    uint32_t acc[4][4][2];

    for (int kp = 0; kp < 64; kp++) {
        int j0 = 2 * kp, j1 = j0 + 1;
        uint32_t s0 = SBB + (uint32_t)(j0 & 3) * TILEH;
        uint32_t s1 = SBB + (uint32_t)(j1 & 3) * TILEH;

        if (j0 + 2 < 128) {   // prefetch next pair into the other two ring slots
            const char* p0 = (const char*)(g_eh + (size_t)(j0 + 2) * 128 * RH);
            uint32_t d0 = SBB + (uint32_t)((j0 + 2) & 3) * TILEH;
            for (int i = tid; i < CHUNKH; i += 256) CP_ASYNC16(d0 + i * 16, p0 + i * 16);
            const char* p1 = (const char*)(g_eh + (size_t)(j1 + 2) * 128 * RH);
            uint32_t d1 = SBB + (uint32_t)((j1 + 2) & 3) * TILEH;
            for (int i = tid; i < CHUNKH; i += 256) CP_ASYNC16(d1 + i * 16, p1 + i * 16);
            CP_COMMIT();
        }

#pragma unroll
        for (int half = 0; half < 2; half++) {
            int j = half ? j1 : j0;
            uint32_t bb = (half ? s1 : s0) + b_roff;
            float en[8];
            load_en(j, nbw, lane, en);
            mma_phase_h16(a_base, bb, acc);
#pragma unroll
            for (int mi = 0; mi < 4; mi++) {
#pragma unroll
                for (int rh = 0; rh < 2; rh++) {
                    float2 f0 = h2f(acc[mi][0][rh]), f1 = h2f(acc[mi][1][rh]);
                    float2 f2 = h2f(acc[mi][2][rh]), f3 = h2f(acc[mi][3][rh]);
                    float q0 = fmaf(f0.x, -0x1p-11f, en[0]);
                    float q1 = fmaf(f0.y, -0x1p-11f, en[1]);
                    float q2 = fmaf(f1.x, -0x1p-11f, en[2]);
                    float q3 = fmaf(f1.y, -0x1p-11f, en[3]);
                    float q4 = fmaf(f2.x, -0x1p-11f, en[4]);
                    float q5 = fmaf(f2.y, -0x1p-11f, en[5]);
                    float q6 = fmaf(f3.x, -0x1p-11f, en[6]);
                    float q7 = fmaf(f3.y, -0x1p-11f, en[7]);
                    float m8 = fminf(fminf(fminf(q0, q1), fminf(q2, q3)),
                                     fminf(fminf(q4, q5), fminf(q6, q7)));
                    bv[mi * 2 + rh] = fminf(bv[mi * 2 + rh], m8);
                }
            }
        }

        CP_WAIT0();
        __syncthreads();
    }

    // quad reduce then cross-warp reduce -> per-token threshold
#pragma unroll
    for (int r = 0; r < 8; r++) {
        bv[r] = fminf(bv[r], __shfl_xor_sync(0xffffffffu, bv[r], 1));
        bv[r] = fminf(bv[r], __shfl_xor_sync(0xffffffffu, bv[r], 2));
    }
    __syncthreads();
    float* rv = (float*)sm;                          // 128 rows x 4 nwarps
    if ((lane & 3) == 0) {
#pragma unroll
        for (int r = 0; r < 8; r++) {
            int row = mbase + (r >> 1) * 16 + (r & 1) * 8 + (lane >> 2);
            rv[row * 4 + nw] = bv[r];
        }
    }
    __syncthreads();
    if (tid < 128) {
        float v = fminf(fminf(rv[tid * 4], rv[tid * 4 + 1]),
                        fminf(rv[tid * 4 + 2], rv[tid * 4 + 3]));
        int t = (blockIdx.x << 7) + tid;
        float zn = g_znorm[t];
        g_thr[t] = v + fmaf(sqrtf(zn), MK1, MK2);
    }
}

// ---------------- pass B: identical GEMM, collect candidates vs final threshold ----
__global__ void __launch_bounds__(256, 1) k_coll() {
    extern __shared__ __align__(16) unsigned char sm[];
    uint32_t sb = smem_u32(sm);
    const uint32_t SA = sb, SBB = sb + TILEH;

    int tid = threadIdx.x, lane = tid & 31, wid = tid >> 5;
    int mw = wid & 1, nw = wid >> 1;
    int mbase = mw * 64, nbw = nw * 32;

    {
        const char* gz = (const char*)(g_zh + (size_t)blockIdx.x * 128 * RH);
        for (int i = tid; i < CHUNKH; i += 256) CP_ASYNC16(SA + i * 16, gz + i * 16);
        const char* ge0 = (const char*)g_eh;
        for (int i = tid; i < CHUNKH; i += 256) CP_ASYNC16(SBB + i * 16, ge0 + i * 16);
        const char* ge1 = (const char*)(g_eh + (size_t)128 * RH);
        for (int i = tid; i < CHUNKH; i += 256) CP_ASYNC16(SBB + TILEH + i * 16, ge1 + i * 16);
        CP_COMMIT(); CP_WAIT0();
    }
    __syncthreads();

    float thr[8]; int tok[8];
#pragma unroll
    for (int mi = 0; mi < 4; mi++)
#pragma unroll
        for (int rh = 0; rh < 2; rh++) {
            int t = (blockIdx.x << 7) + mbase + mi * 16 + rh * 8 + (lane >> 2);
            tok[mi * 2 + rh] = t;
            thr[mi * 2 + rh] = g_thr[t];
        }

    uint32_t a_base = SA + (uint32_t)(mbase + (lane & 15)) * RBH + ((lane >> 4) & 1) * 16;
    uint32_t b_roff = (uint32_t)(nbw + (lane & 7)) * RBH + ((lane >> 3) & 1) * 16;

    uint32_t acc[4][4][2];

    for (int kp = 0; kp < 64; kp++) {
        int j0 = 2 * kp, j1 = j0 + 1;
        uint32_t s0 = SBB + (uint32_t)(j0 & 3) * TILEH;
        uint32_t s1 = SBB + (uint32_t)(j1 & 3) * TILEH;

        if (j0 + 2 < 128) {
            const char* p0 = (const char*)(g_eh + (size_t)(j0 + 2) * 128 * RH);
            uint32_t d0 = SBB + (uint32_t)((j0 + 2) & 3) * TILEH;
            for (int i = tid; i < CHUNKH; i += 256) CP_ASYNC16(d0 + i * 16, p0 + i * 16);
            const char* p1 = (const char*)(g_eh + (size_t)(j1 + 2) * 128 * RH);
            uint32_t d1 = SBB + (uint32_t)((j1 + 2) & 3) * TILEH;
            for (int i = tid; i < CHUNKH; i += 256) CP_ASYNC16(d1 + i * 16, p1 + i * 16);
            CP_COMMIT();
        }

#pragma unroll
        for (int half = 0; half < 2; half++) {
            int j = half ? j1 : j0;
            uint32_t bb = (half ? s1 : s0) + b_roff;
            float en[8];
            load_en(j, nbw, lane, en);
            mma_phase_h16(a_base, bb, acc);
            int jbase = j << 7;
#pragma unroll
            for (int mi = 0; mi < 4; mi++) {
#pragma unroll
                for (int rh = 0; rh < 2; rh++) {
                    int r = mi * 2 + rh;
                    float2 f0 = h2f(acc[mi][0][rh]), f1 = h2f(acc[mi][1][rh]);
                    float2 f2 = h2f(acc[mi][2][rh]), f3 = h2f(acc[mi][3][rh]);
                    float q[8];
                    q[0] = fmaf(f0.x, -0x1p-11f, en[0]);
                    q[1] = fmaf(f0.y, -0x1p-11f, en[1]);
                    q[2] = fmaf(f1.x, -0x1p-11f, en[2]);
                    q[3] = fmaf(f1.y, -0x1p-11f, en[3]);
                    q[4] = fmaf(f2.x, -0x1p-11f, en[4]);
                    q[5] = fmaf(f2.y, -0x1p-11f, en[5]);
                    q[6] = fmaf(f3.x, -0x1p-11f, en[6]);
                    q[7] = fmaf(f3.y, -0x1p-11f, en[7]);
                    float m8 = fminf(fminf(fminf(q[0], q[1]), fminf(q[2], q[3])),
                                     fminf(fminf(q[4], q[5]), fminf(q[6], q[7])));
                    if (m8 <= thr[r]) {     // rare: threshold = final min + margin
                        int t = tok[r];
#pragma unroll
                        for (int ni = 0; ni < 4; ni++)
#pragma unroll
                            for (int col = 0; col < 2; col++) {
                                if (q[ni * 2 + col] <= thr[r]) {
                                    int n = jbase + nbw + ni * 8 + (lane & 3) * 2 + col;
                                    int slot = atomicAdd(&g_ccnt[t], 1);
                                    if (slot < CAP) g_cand[t * CAP + slot] = n;
                                }
                            }
                    }
                }
            }
        }

        CP_WAIT0();
        __syncthreads();
    }
}

// ---------------- pass C: exact fp32 refine over candidates (R1 formula) -----------
__global__ void k_refine(const float* __restrict__ z, const float* __restrict__ emb,
                         float* __restrict__ out) {
    __shared__ float zs[8][64];
    int w = threadIdx.x >> 5, lane = threadIdx.x & 31;
    int t = blockIdx.x * 8 + w;
    int b = t >> 10, hw = t & 1023;
    zs[w][lane]      = z[((size_t)(b * 64 + lane) << 10) + hw];
    zs[w][lane + 32] = z[((size_t)(b * 64 + lane + 32) << 10) + hw];
    __syncwarp();
    float zn = g_znorm[t];
    int c = g_ccnt[t];
    float bd = 3.0e38f; int bn = 0x7fffffff;
    if (c <= CAP) {
        for (int i = lane; i < c; i += 32) {
            int n = g_cand[t * CAP + i];
            const float* er = emb + (size_t)n * 64;
            float acc = 0.f;
#pragma unroll
            for (int k = 0; k < 64; k++) acc = fmaf(zs[w][k], er[k], acc);
            float d = __fsub_rn(__fadd_rn(zn, g_enorm[n]), __fmul_rn(2.0f, acc));
            if (d < bd || (d == bd && n < bn)) { bd = d; bn = n; }
        }
    } else {
        // overflow fallback: exact scan of all codes (correctness net)
        for (int n = lane; n < NE; n += 32) {
            const float* er = emb + (size_t)n * 64;
            float acc = 0.f;
#pragma unroll
            for (int k = 0; k < 64; k++) acc = fmaf(zs[w][k], er[k], acc);
            float d = __fsub_rn(__fadd_rn(zn, g_enorm[n]), __fmul_rn(2.0f, acc));
            if (d < bd || (d == bd && n < bn)) { bd = d; bn = n; }
        }
    }
#pragma unroll
    for (int off = 16; off > 0; off >>= 1) {
        float od = __shfl_xor_sync(0xffffffffu, bd, off);
        int   on = __shfl_xor_sync(0xffffffffu, bn, off);
        if (od < bd || (od == bd && on < bn)) { bd = od; bn = on; }
    }
    if (lane == 0) {
        g_idx[t] = bn;
        out[1048579 + t] = (float)bn;
        atomicAdd(&g_counts[bn], 1);
    }
}

// ---------------- z_q gather + loss accumulation ----------------
__global__ void k_zq(const float* __restrict__ z, const float* __restrict__ emb,
                     float* __restrict__ out) {
    int p = blockIdx.x;            // 1024 planes = (b,c)
    int b = p >> 6, c = p & 63;
    int tid = threadIdx.x;         // 256
    float ls = 0.f;
    for (int hw = tid; hw < 1024; hw += 256) {
        int t = (b << 10) + hw;
        int id = g_idx[t];
        float v  = emb[(size_t)id * 64 + c];
        float zv = z[(size_t)p * 1024 + hw];
        out[(size_t)p * 1024 + hw] = v;
        float df = v - zv;
        ls += df * df;
    }
    __shared__ float red[8];
    for (int o = 16; o > 0; o >>= 1) ls += __shfl_down_sync(0xffffffff, ls, o);
    if ((tid & 31) == 0) red[tid >> 5] = ls;
    __syncthreads();
    if (tid == 0) {
        float s = 0.f;
        for (int w = 0; w < 8; w++) s += red[w];
        atomicAdd(&g_loss, s);
    }
}

// ---------------- entropy (parallel) + final scalar writes (ticket) ----------------
__global__ void k_ent(float* __restrict__ out) {
    int tid = threadIdx.x;                      // 1024, grid 16
    int n = blockIdx.x * 1024 + tid;
    int c = g_counts[n];
    float avg = (float)c * (1.0f / 16384.0f);
    float term = avg * logf(avg + 1e-10f);
    int cu = (c > 0) ? 1 : 0;
    for (int o = 16; o > 0; o >>= 1) {
        term += __shfl_down_sync(0xffffffffu, term, o);
        cu   += __shfl_down_sync(0xffffffffu, cu, o);
    }
    __shared__ float se[32]; __shared__ int sc[32];
    if ((tid & 31) == 0) { se[tid >> 5] = term; sc[tid >> 5] = cu; }
    __syncthreads();
    if (tid == 0) {
        float s = 0.f; int k = 0;
        for (int w = 0; w < 32; w++) { s += se[w]; k += sc[w]; }
        atomicAdd(&g_ent, s);
        atomicAdd(&g_cu, k);
        __threadfence();
        int tk = atomicAdd(&g_tick, 1);
        if (tk == 15) {
            out[1048576] = g_loss * (1.0f + BETA) / 1048576.0f;
            out[1048577] = expf(-g_ent);
            out[1048578] = (float)g_cu;
        }
    }
}

// ---------------- launch ----------------
extern "C" void kernel_launch(void* const* d_in, const int* in_sizes, int n_in,
                              void* d_out, int out_size) {
    const float* z   = (const float*)d_in[0];   // (16,64,32,32)
    const float* emb = (const float*)d_in[1];   // (16384,64)
    float* out = (float*)d_out;

    cudaFuncSetAttribute(k_split, cudaFuncAttributeMaxDynamicSharedMemorySize, TILEH);
    cudaFuncSetAttribute(k_min,   cudaFuncAttributeMaxDynamicSharedMemorySize, SM_F);
    cudaFuncSetAttribute(k_coll,  cudaFuncAttributeMaxDynamicSharedMemorySize, SM_F);

    k_split<<<256, 256, TILEH>>>(z, emb);
    k_min<<<128, 256, SM_F>>>();
    k_coll<<<128, 256, SM_F>>>();
    k_refine<<<2048, 256>>>(z, emb, out);
    k_zq<<<1024, 256>>>(z, emb, out);
    k_ent<<<16, 1024>>>(out);
}